// round 1
// baseline (speedup 1.0000x reference)
#include <cuda_runtime.h>
#include <math.h>

// Problem-fixed shapes (validated against in_sizes at launch).
#define T_MAX 4096
#define E_NUM 8
#define D_DIM 1024
#define F_DIM 4096

// ---------------- scratch (static device globals; no allocs) ----------------
__device__ int   g_cnt[E_NUM];                       // tokens per expert
__device__ int   g_tok[E_NUM * T_MAX];               // token id per (e, slot)
__device__ int   g_aid[E_NUM * T_MAX];               // assignment id (t*2+j)
__device__ float g_gate[2 * T_MAX];                  // gate per assignment
__device__ float g_h[(size_t)2 * T_MAX * F_DIM];     // 128 MB: gelu(x W1 + b1)
__device__ float g_y[(size_t)2 * T_MAX * D_DIM];     //  32 MB: h W2 + b2

// ---------------- init ----------------
__global__ void init_kernel() {
    if (threadIdx.x < E_NUM) g_cnt[threadIdx.x] = 0;
}

// ---------------- router: logits -> softmax -> top-2 gates + expert lists ----------------
__global__ void router_kernel(const float* __restrict__ x,
                              const float* __restrict__ Wr,
                              const float* __restrict__ br, int T) {
    int warp = threadIdx.x >> 5;
    int lane = threadIdx.x & 31;
    int t = blockIdx.x * 8 + warp;
    if (t >= T) return;

    const float* xr = x + (size_t)t * D_DIM;
    float acc[E_NUM];
#pragma unroll
    for (int e = 0; e < E_NUM; e++) acc[e] = 0.f;

    for (int i = lane; i < D_DIM; i += 32) {
        float xv = xr[i];
        float4 w0 = *(const float4*)(Wr + (size_t)i * E_NUM);
        float4 w1 = *(const float4*)(Wr + (size_t)i * E_NUM + 4);
        acc[0] += xv * w0.x; acc[1] += xv * w0.y;
        acc[2] += xv * w0.z; acc[3] += xv * w0.w;
        acc[4] += xv * w1.x; acc[5] += xv * w1.y;
        acc[6] += xv * w1.z; acc[7] += xv * w1.w;
    }
#pragma unroll
    for (int e = 0; e < E_NUM; e++) {
#pragma unroll
        for (int off = 16; off > 0; off >>= 1)
            acc[e] += __shfl_down_sync(0xffffffffu, acc[e], off);
    }

    if (lane == 0) {
        float l[E_NUM], p[E_NUM];
        float mx = -1e30f;
#pragma unroll
        for (int e = 0; e < E_NUM; e++) { l[e] = acc[e] + br[e]; mx = fmaxf(mx, l[e]); }
        float s = 0.f;
#pragma unroll
        for (int e = 0; e < E_NUM; e++) { p[e] = expf(l[e] - mx); s += p[e]; }
        float inv = 1.f / s;
#pragma unroll
        for (int e = 0; e < E_NUM; e++) p[e] *= inv;

        // 2nd-largest prob = threshold (matches probs >= kth in reference)
        float m1 = -1.f, m2 = -1.f;
#pragma unroll
        for (int e = 0; e < E_NUM; e++) {
            float v = p[e];
            if (v > m1) { m2 = m1; m1 = v; }
            else if (v > m2) { m2 = v; }
        }
        float kth = m2;

        int j = 0;
#pragma unroll
        for (int e = 0; e < E_NUM; e++) {
            if (p[e] >= kth && j < 2) {
                int slot = atomicAdd(&g_cnt[e], 1);
                g_tok[e * T_MAX + slot] = t;
                g_aid[e * T_MAX + slot] = t * 2 + j;
                g_gate[t * 2 + j] = p[e];
                j++;
            }
        }
    }
}

// ---------------- grouped SGEMM: 128x128 tile, 8x8 per thread, K-tile 8 ----------------
// A_FROM_H=false: A = x (gather rows by g_tok), C = g_h, GELU epilogue, K=1024, N=4096
// A_FROM_H=true : A = g_h (gather rows by g_aid), C = g_y, bias-only epilogue, K=4096, N=1024
template <int K, int N, bool GELU, bool A_FROM_H>
__global__ __launch_bounds__(256)
void moe_gemm(const float* __restrict__ x,
              const float* __restrict__ B_all,     // W1 or W2 (E-major)
              const float* __restrict__ bias_all)  // b1 [E,N] or b2 [E,N]
{
    __shared__ float As[8][132];
    __shared__ float Bs[8][128];

    const int e   = blockIdx.z;
    const int cnt = g_cnt[e];
    const int m0  = blockIdx.y * 128;
    if (m0 >= cnt) return;
    const int n0  = blockIdx.x * 128;

    const int tid = threadIdx.x;
    const int tx  = tid & 15;     // N micro-tile
    const int ty  = tid >> 4;     // M micro-tile

    // A-load mapping: 128 rows x 8 k, two float4 groups per row
    const int arow = tid >> 1;
    const int ak   = (tid & 1) << 2;
    const int gm   = m0 + arow;
    const bool avalid = (gm < cnt);
    const int* rows_in = A_FROM_H ? g_aid : g_tok;
    const float* A = A_FROM_H ? g_h : x;
    size_t asrc = 0;
    if (avalid) asrc = (size_t)rows_in[e * T_MAX + gm] * K;

    // B-load mapping: 8 k x 128 n, one float4 per thread
    const int bk = tid >> 5;
    const int bn = (tid & 31) << 2;
    const float* Bp = B_all + (size_t)e * K * N + (size_t)bk * N + n0 + bn;

    float acc[8][8];
#pragma unroll
    for (int i = 0; i < 8; i++)
#pragma unroll
        for (int j = 0; j < 8; j++) acc[i][j] = 0.f;

    for (int k0 = 0; k0 < K; k0 += 8) {
        float4 av = make_float4(0.f, 0.f, 0.f, 0.f);
        if (avalid) av = *(const float4*)(A + asrc + k0 + ak);
        float4 bv = *(const float4*)(Bp + (size_t)k0 * N);

        As[ak + 0][arow] = av.x;
        As[ak + 1][arow] = av.y;
        As[ak + 2][arow] = av.z;
        As[ak + 3][arow] = av.w;
        *(float4*)&Bs[bk][bn] = bv;
        __syncthreads();

#pragma unroll
        for (int kk = 0; kk < 8; kk++) {
            float4 a0 = *(const float4*)&As[kk][ty * 8];
            float4 a1 = *(const float4*)&As[kk][ty * 8 + 4];
            float4 b0 = *(const float4*)&Bs[kk][tx * 8];
            float4 b1 = *(const float4*)&Bs[kk][tx * 8 + 4];
            float a[8] = {a0.x, a0.y, a0.z, a0.w, a1.x, a1.y, a1.z, a1.w};
            float b[8] = {b0.x, b0.y, b0.z, b0.w, b1.x, b1.y, b1.z, b1.w};
#pragma unroll
            for (int i = 0; i < 8; i++)
#pragma unroll
                for (int j = 0; j < 8; j++) acc[i][j] = fmaf(a[i], b[j], acc[i][j]);
        }
        __syncthreads();
    }

    // epilogue
    float* C = GELU ? g_h : g_y;
    const float* brow = bias_all + (size_t)e * N + n0 + tx * 8;
    float bj[8];
#pragma unroll
    for (int j = 0; j < 8; j++) bj[j] = brow[j];

#pragma unroll
    for (int i = 0; i < 8; i++) {
        int gmr = m0 + ty * 8 + i;
        if (gmr >= cnt) continue;
        int aid = g_aid[e * T_MAX + gmr];
        float* crow = C + (size_t)aid * N + n0 + tx * 8;
        float v[8];
#pragma unroll
        for (int j = 0; j < 8; j++) {
            float w = acc[i][j] + bj[j];
            if (GELU) w = 0.5f * w * (1.f + erff(w * 0.70710678118654752f));
            v[j] = w;
        }
        *(float4*)(crow)     = make_float4(v[0], v[1], v[2], v[3]);
        *(float4*)(crow + 4) = make_float4(v[4], v[5], v[6], v[7]);
    }
}

// ---------------- combine: out[t] = g0*y[2t] + g1*y[2t+1] ----------------
__global__ void combine_kernel(float* __restrict__ out, int T) {
    int i = blockIdx.x * blockDim.x + threadIdx.x;        // over T * D/4
    int total = T * (D_DIM / 4);
    if (i >= total) return;
    int t  = i / (D_DIM / 4);
    int c4 = i % (D_DIM / 4);
    float g0 = g_gate[2 * t], g1 = g_gate[2 * t + 1];
    const float4 y0 = *(const float4*)(g_y + (size_t)(2 * t) * D_DIM + c4 * 4);
    const float4 y1 = *(const float4*)(g_y + (size_t)(2 * t + 1) * D_DIM + c4 * 4);
    float4 o;
    o.x = g0 * y0.x + g1 * y1.x;
    o.y = g0 * y0.y + g1 * y1.y;
    o.z = g0 * y0.z + g1 * y1.z;
    o.w = g0 * y0.w + g1 * y1.w;
    ((float4*)out)[i] = o;
}

// ---------------- entry ----------------
extern "C" void kernel_launch(void* const* d_in, const int* in_sizes, int n_in,
                              void* d_out, int out_size) {
    const float* x  = (const float*)d_in[0];
    const float* Wr = (const float*)d_in[1];
    const float* br = (const float*)d_in[2];
    const float* W1 = (const float*)d_in[3];
    const float* b1 = (const float*)d_in[4];
    const float* W2 = (const float*)d_in[5];
    const float* b2 = (const float*)d_in[6];
    (void)n_in;

    const int T = in_sizes[0] / D_DIM;   // 4096

    init_kernel<<<1, 32>>>();
    router_kernel<<<(T + 7) / 8, 256>>>(x, Wr, br, T);

    // layer 1: [cnt_e,1024] x [1024,4096] -> gelu -> g_h
    dim3 grid1(F_DIM / 128, T / 128, E_NUM);
    moe_gemm<D_DIM, F_DIM, true, false><<<grid1, 256>>>(x, W1, b1);

    // layer 2: [cnt_e,4096] x [4096,1024] -> +b2 -> g_y
    dim3 grid2(D_DIM / 128, T / 128, E_NUM);
    moe_gemm<F_DIM, D_DIM, false, true><<<grid2, 256>>>(x, W2, b2);

    // combine with gates
    int total = T * (D_DIM / 4);
    combine_kernel<<<(total + 255) / 256, 256>>>((float*)d_out, T);
    (void)out_size;
}

// round 3
// speedup vs baseline: 2.1668x; 2.1668x over previous
#include <cuda_runtime.h>
#include <cuda_fp16.h>
#include <math.h>
#include <stdint.h>

#define T_MAX 4096
#define E_NUM 8
#define D_DIM 1024
#define F_DIM 4096

// ---------------- scratch (static device globals; no allocs) ----------------
__device__ int   g_cnt[E_NUM];
__device__ int   g_tok[E_NUM * T_MAX];
__device__ int   g_aid[E_NUM * T_MAX];
__device__ float g_gate[2 * T_MAX];
// split fp16 weights, transposed to [E][N][K]
__device__ __half g_W1h[(size_t)E_NUM * F_DIM * D_DIM];
__device__ __half g_W1l[(size_t)E_NUM * F_DIM * D_DIM];
__device__ __half g_W2h[(size_t)E_NUM * D_DIM * F_DIM];
__device__ __half g_W2l[(size_t)E_NUM * D_DIM * F_DIM];
// hidden activations, split fp16: [2T][F]
__device__ __half g_hh[(size_t)2 * T_MAX * F_DIM];
__device__ __half g_hl[(size_t)2 * T_MAX * F_DIM];
__device__ float  g_y[(size_t)2 * T_MAX * D_DIM];

// ---------------- helpers ----------------
__device__ __forceinline__ uint32_t smem_u32(const void* p) {
    return (uint32_t)__cvta_generic_to_shared(p);
}
__device__ __forceinline__ void ldmat4(uint32_t (&r)[4], uint32_t addr) {
    asm volatile("ldmatrix.sync.aligned.m8n8.x4.shared.b16 {%0,%1,%2,%3}, [%4];"
        : "=r"(r[0]), "=r"(r[1]), "=r"(r[2]), "=r"(r[3]) : "r"(addr));
}
__device__ __forceinline__ void mma16816(float (&d)[4], const uint32_t (&a)[4],
                                         uint32_t b0, uint32_t b1) {
    asm volatile("mma.sync.aligned.m16n8k16.row.col.f32.f16.f16.f32 "
        "{%0,%1,%2,%3}, {%4,%5,%6,%7}, {%8,%9}, {%0,%1,%2,%3};"
        : "+f"(d[0]), "+f"(d[1]), "+f"(d[2]), "+f"(d[3])
        : "r"(a[0]), "r"(a[1]), "r"(a[2]), "r"(a[3]), "r"(b0), "r"(b1));
}
__device__ __forceinline__ uint32_t packh2(float a, float b) {
    __half2 h = __floats2half2_rn(a, b);
    return *(uint32_t*)&h;
}
__device__ __forceinline__ void splith(float v, __half& h, float& lo) {
    h = __float2half_rn(v);
    lo = v - __half2float(h);
}

// ---------------- init ----------------
__global__ void init_kernel() {
    if (threadIdx.x < E_NUM) g_cnt[threadIdx.x] = 0;
}

// ---------------- router ----------------
__global__ void router_kernel(const float* __restrict__ x,
                              const float* __restrict__ Wr,
                              const float* __restrict__ br, int T) {
    int warp = threadIdx.x >> 5;
    int lane = threadIdx.x & 31;
    int t = blockIdx.x * 8 + warp;
    if (t >= T) return;

    const float* xr = x + (size_t)t * D_DIM;
    float acc[E_NUM];
#pragma unroll
    for (int e = 0; e < E_NUM; e++) acc[e] = 0.f;
    for (int i = lane; i < D_DIM; i += 32) {
        float xv = xr[i];
        float4 w0 = *(const float4*)(Wr + (size_t)i * E_NUM);
        float4 w1 = *(const float4*)(Wr + (size_t)i * E_NUM + 4);
        acc[0] += xv * w0.x; acc[1] += xv * w0.y;
        acc[2] += xv * w0.z; acc[3] += xv * w0.w;
        acc[4] += xv * w1.x; acc[5] += xv * w1.y;
        acc[6] += xv * w1.z; acc[7] += xv * w1.w;
    }
#pragma unroll
    for (int e = 0; e < E_NUM; e++)
#pragma unroll
        for (int off = 16; off > 0; off >>= 1)
            acc[e] += __shfl_down_sync(0xffffffffu, acc[e], off);

    if (lane == 0) {
        float l[E_NUM], p[E_NUM];
        float mx = -1e30f;
#pragma unroll
        for (int e = 0; e < E_NUM; e++) { l[e] = acc[e] + br[e]; mx = fmaxf(mx, l[e]); }
        float s = 0.f;
#pragma unroll
        for (int e = 0; e < E_NUM; e++) { p[e] = expf(l[e] - mx); s += p[e]; }
        float inv = 1.f / s;
#pragma unroll
        for (int e = 0; e < E_NUM; e++) p[e] *= inv;
        float m1 = -1.f, m2 = -1.f;
#pragma unroll
        for (int e = 0; e < E_NUM; e++) {
            float v = p[e];
            if (v > m1) { m2 = m1; m1 = v; }
            else if (v > m2) { m2 = v; }
        }
        int j = 0;
#pragma unroll
        for (int e = 0; e < E_NUM; e++) {
            if (p[e] >= m2 && j < 2) {
                int slot = atomicAdd(&g_cnt[e], 1);
                g_tok[e * T_MAX + slot] = t;
                g_aid[e * T_MAX + slot] = t * 2 + j;
                g_gate[t * 2 + j] = p[e];
                j++;
            }
        }
    }
}

// ---------------- weight prep: fp32 [E][K][N] -> fp16 hi/lo [E][N][K] ----------------
__global__ void wprep_kernel(const float* __restrict__ W,
                             __half* __restrict__ Wh,
                             __half* __restrict__ Wl, int K, int N) {
    __shared__ float tile[32][33];
    int e = blockIdx.z;
    int n0 = blockIdx.x * 32;
    int k0 = blockIdx.y * 32;
#pragma unroll
    for (int r = 0; r < 4; r++) {
        int k = k0 + threadIdx.y + r * 8;
        tile[threadIdx.y + r * 8][threadIdx.x] =
            W[((size_t)e * K + k) * N + n0 + threadIdx.x];
    }
    __syncthreads();
#pragma unroll
    for (int r = 0; r < 4; r++) {
        int n = n0 + threadIdx.y + r * 8;
        int k = k0 + threadIdx.x;
        float v = tile[threadIdx.x][threadIdx.y + r * 8];
        __half h; float lo;
        splith(v, h, lo);
        size_t o = ((size_t)e * N + n) * K + k;
        Wh[o] = h; Wl[o] = __float2half_rn(lo);
    }
}

// ---------------- grouped MMA GEMM ----------------
// CTA tile 128(M) x 128(N), K staged by 32, double-buffered.
// A_IS_H=false: A = gathered x rows (fp32, split on the fly), GELU epi -> g_hh/g_hl
// A_IS_H=true : A = gathered g_hh/g_hl rows, bias epi -> g_y
template <int K, int NTOT, bool GELU_EPI, bool A_IS_H>
__global__ __launch_bounds__(256, 1)
void moe_mma(const float* __restrict__ x,
             const __half* __restrict__ Bh_all,
             const __half* __restrict__ Bl_all,
             const float* __restrict__ bias_all) {
    constexpr int S = K / 32;
    constexpr int PITCH = 40;                 // halfs per row (conflict-free ldmatrix)
    constexpr int TILE_B = 128 * PITCH * 2;   // 10240 bytes per sub-tile
    constexpr int STAGE = 4 * TILE_B;         // Ah, Al, Bh, Bl
    extern __shared__ char sm[];

    const int e = blockIdx.z;
    const int cnt = g_cnt[e];
    const int m0 = blockIdx.y * 128;
    if (m0 >= cnt) return;
    const int n0 = blockIdx.x * 128;

    const int tid = threadIdx.x, wid = tid >> 5, lane = tid & 31;
    const int wm = wid & 3, wn = wid >> 2;    // warp grid 4(M) x 2(N)

    // global staging: thread -> (row tid/2, k-half tid%2 of the 32-k stage)
    const int grow = tid >> 1, gh = tid & 1;
    const bool avalid = (m0 + grow) < cnt;
    size_t arow_off = 0;
    if (avalid) {
        int ridx = A_IS_H ? g_aid[e * T_MAX + m0 + grow] : g_tok[e * T_MAX + m0 + grow];
        arow_off = (size_t)ridx * K;
    }
    const size_t brow_off = ((size_t)e * NTOT + n0 + grow) * K;
    const uint32_t st_off = (uint32_t)grow * (PITCH * 2) + gh * 32;

    // ldmatrix lane addressing
    const int a_r = (lane & 7) + ((lane >> 3) & 1) * 8;
    const int a_c = lane >> 4;
    const int b_r = (lane & 7) + ((lane >> 4) << 3);
    const int b_c = (lane >> 3) & 1;

    float acc[2][8][4];
#pragma unroll
    for (int i = 0; i < 2; i++)
#pragma unroll
        for (int j = 0; j < 8; j++)
#pragma unroll
            for (int q = 0; q < 4; q++) acc[i][j][q] = 0.f;

    float4 afv[4];
    uint4 ahv[2], alv[2], bhv[2], blv[2];

    auto load_stage = [&](int k0) {
        const uint4* bh = (const uint4*)(Bh_all + brow_off + k0 + gh * 16);
        const uint4* bl = (const uint4*)(Bl_all + brow_off + k0 + gh * 16);
        bhv[0] = bh[0]; bhv[1] = bh[1];
        blv[0] = bl[0]; blv[1] = bl[1];
        if (A_IS_H) {
            const uint4* ah = (const uint4*)(g_hh + arow_off + k0 + gh * 16);
            const uint4* al = (const uint4*)(g_hl + arow_off + k0 + gh * 16);
            uint4 z = make_uint4(0, 0, 0, 0);
            ahv[0] = avalid ? ah[0] : z; ahv[1] = avalid ? ah[1] : z;
            alv[0] = avalid ? al[0] : z; alv[1] = avalid ? al[1] : z;
        } else {
            const float4* ax = (const float4*)(x + arow_off + k0 + gh * 16);
            float4 z = make_float4(0.f, 0.f, 0.f, 0.f);
#pragma unroll
            for (int i = 0; i < 4; i++) afv[i] = avalid ? ax[i] : z;
        }
    };

    auto store_stage = [&](int b) {
        char* ah = sm + b * STAGE;
        char* al = ah + TILE_B;
        char* bh = ah + 2 * TILE_B;
        char* bl = ah + 3 * TILE_B;
        *(uint4*)(bh + st_off) = bhv[0]; *(uint4*)(bh + st_off + 16) = bhv[1];
        *(uint4*)(bl + st_off) = blv[0]; *(uint4*)(bl + st_off + 16) = blv[1];
        if (A_IS_H) {
            *(uint4*)(ah + st_off) = ahv[0]; *(uint4*)(ah + st_off + 16) = ahv[1];
            *(uint4*)(al + st_off) = alv[0]; *(uint4*)(al + st_off + 16) = alv[1];
        } else {
            uint32_t hu[8], lu[8];
#pragma unroll
            for (int q = 0; q < 4; q++) {
                __half h0, h1, h2, h3; float l0, l1, l2, l3;
                splith(afv[q].x, h0, l0); splith(afv[q].y, h1, l1);
                splith(afv[q].z, h2, l2); splith(afv[q].w, h3, l3);
                __half2 p01 = __halves2half2(h0, h1);
                __half2 p23 = __halves2half2(h2, h3);
                hu[2 * q]     = *(uint32_t*)&p01;
                hu[2 * q + 1] = *(uint32_t*)&p23;
                lu[2 * q]     = packh2(l0, l1);
                lu[2 * q + 1] = packh2(l2, l3);
            }
            *(uint4*)(ah + st_off)      = make_uint4(hu[0], hu[1], hu[2], hu[3]);
            *(uint4*)(ah + st_off + 16) = make_uint4(hu[4], hu[5], hu[6], hu[7]);
            *(uint4*)(al + st_off)      = make_uint4(lu[0], lu[1], lu[2], lu[3]);
            *(uint4*)(al + st_off + 16) = make_uint4(lu[4], lu[5], lu[6], lu[7]);
        }
    };

    auto compute_stage = [&](int b) {
        uint32_t ahb = smem_u32(sm + b * STAGE);
        uint32_t alb = ahb + TILE_B, bhb = ahb + 2 * TILE_B, blb = ahb + 3 * TILE_B;
#pragma unroll
        for (int ks = 0; ks < 2; ks++) {
            uint32_t a_hi[2][4], a_lo[2][4];
#pragma unroll
            for (int mt = 0; mt < 2; mt++) {
                uint32_t off = (uint32_t)((wm * 32 + mt * 16 + a_r) * PITCH + ks * 16 + a_c * 8) * 2;
                ldmat4(a_hi[mt], ahb + off);
                ldmat4(a_lo[mt], alb + off);
            }
#pragma unroll
            for (int nb = 0; nb < 4; nb++) {
                uint32_t off = (uint32_t)((wn * 64 + nb * 16 + b_r) * PITCH + ks * 16 + b_c * 8) * 2;
                uint32_t b_hi[4], b_lo[4];
                ldmat4(b_hi, bhb + off);
                ldmat4(b_lo, blb + off);
#pragma unroll
                for (int mt = 0; mt < 2; mt++) {
                    mma16816(acc[mt][2 * nb],     a_hi[mt], b_hi[0], b_hi[1]);
                    mma16816(acc[mt][2 * nb + 1], a_hi[mt], b_hi[2], b_hi[3]);
                    mma16816(acc[mt][2 * nb],     a_hi[mt], b_lo[0], b_lo[1]);
                    mma16816(acc[mt][2 * nb + 1], a_hi[mt], b_lo[2], b_lo[3]);
                    mma16816(acc[mt][2 * nb],     a_lo[mt], b_hi[0], b_hi[1]);
                    mma16816(acc[mt][2 * nb + 1], a_lo[mt], b_hi[2], b_hi[3]);
                }
            }
        }
    };

    load_stage(0);
    for (int s = 0; s < S; s++) {
        store_stage(s & 1);
        __syncthreads();
        if (s + 1 < S) load_stage((s + 1) * 32);
        compute_stage(s & 1);
        if (s + 1 < S) __syncthreads();
    }

    // ---- epilogue ----
    const int r_l = lane >> 2, c_l = (lane & 3) * 2;
    const float* bias = bias_all + (size_t)e * NTOT;
#pragma unroll
    for (int mt = 0; mt < 2; mt++) {
#pragma unroll
        for (int rh = 0; rh < 2; rh++) {
            int gr = m0 + wm * 32 + mt * 16 + rh * 8 + r_l;
            if (gr >= cnt) continue;
            int aid = g_aid[e * T_MAX + gr];
#pragma unroll
            for (int nc = 0; nc < 8; nc++) {
                int gn = n0 + wn * 64 + nc * 8 + c_l;
                float v0 = acc[mt][nc][rh * 2]     + bias[gn];
                float v1 = acc[mt][nc][rh * 2 + 1] + bias[gn + 1];
                if (GELU_EPI) {
                    v0 = 0.5f * v0 * (1.f + erff(v0 * 0.70710678118654752f));
                    v1 = 0.5f * v1 * (1.f + erff(v1 * 0.70710678118654752f));
                    __half h0, h1; float l0, l1;
                    splith(v0, h0, l0); splith(v1, h1, l1);
                    __half2 hp = __halves2half2(h0, h1);
                    *(uint32_t*)(g_hh + (size_t)aid * NTOT + gn) = *(uint32_t*)&hp;
                    *(uint32_t*)(g_hl + (size_t)aid * NTOT + gn) = packh2(l0, l1);
                } else {
                    *(float2*)(g_y + (size_t)aid * NTOT + gn) = make_float2(v0, v1);
                }
            }
        }
    }
}

// ---------------- combine ----------------
__global__ void combine_kernel(float* __restrict__ out, int T) {
    int i = blockIdx.x * blockDim.x + threadIdx.x;
    int total = T * (D_DIM / 4);
    if (i >= total) return;
    int t = i / (D_DIM / 4);
    int c4 = i % (D_DIM / 4);
    float g0 = g_gate[2 * t], g1 = g_gate[2 * t + 1];
    const float4 y0 = *(const float4*)(g_y + (size_t)(2 * t) * D_DIM + c4 * 4);
    const float4 y1 = *(const float4*)(g_y + (size_t)(2 * t + 1) * D_DIM + c4 * 4);
    float4 o;
    o.x = g0 * y0.x + g1 * y1.x;
    o.y = g0 * y0.y + g1 * y1.y;
    o.z = g0 * y0.z + g1 * y1.z;
    o.w = g0 * y0.w + g1 * y1.w;
    ((float4*)out)[i] = o;
}

// ---------------- entry ----------------
extern "C" void kernel_launch(void* const* d_in, const int* in_sizes, int n_in,
                              void* d_out, int out_size) {
    const float* x  = (const float*)d_in[0];
    const float* Wr = (const float*)d_in[1];
    const float* br = (const float*)d_in[2];
    const float* W1 = (const float*)d_in[3];
    const float* b1 = (const float*)d_in[4];
    const float* W2 = (const float*)d_in[5];
    const float* b2 = (const float*)d_in[6];
    (void)n_in; (void)out_size;

    const int T = in_sizes[0] / D_DIM;

    const int SMEM = 2 * 4 * 128 * 40 * 2;   // 81920
    cudaFuncSetAttribute((const void*)&moe_mma<D_DIM, F_DIM, true, false>,
                         cudaFuncAttributeMaxDynamicSharedMemorySize, SMEM);
    cudaFuncSetAttribute((const void*)&moe_mma<F_DIM, D_DIM, false, true>,
                         cudaFuncAttributeMaxDynamicSharedMemorySize, SMEM);

    init_kernel<<<1, 32>>>();
    router_kernel<<<(T + 7) / 8, 256>>>(x, Wr, br, T);

    __half* W1h; cudaGetSymbolAddress((void**)&W1h, g_W1h);
    __half* W1l; cudaGetSymbolAddress((void**)&W1l, g_W1l);
    __half* W2h; cudaGetSymbolAddress((void**)&W2h, g_W2h);
    __half* W2l; cudaGetSymbolAddress((void**)&W2l, g_W2l);

    wprep_kernel<<<dim3(F_DIM / 32, D_DIM / 32, E_NUM), dim3(32, 8)>>>(W1, W1h, W1l, D_DIM, F_DIM);
    wprep_kernel<<<dim3(D_DIM / 32, F_DIM / 32, E_NUM), dim3(32, 8)>>>(W2, W2h, W2l, F_DIM, D_DIM);

    moe_mma<D_DIM, F_DIM, true, false>
        <<<dim3(F_DIM / 128, T_MAX / 128, E_NUM), 256, SMEM>>>(x, W1h, W1l, b1);
    moe_mma<F_DIM, D_DIM, false, true>
        <<<dim3(D_DIM / 128, T_MAX / 128, E_NUM), 256, SMEM>>>(x, W2h, W2l, b2);

    int total = T * (D_DIM / 4);
    combine_kernel<<<(total + 255) / 256, 256>>>((float*)d_out, T);
}

// round 4
// speedup vs baseline: 3.4590x; 1.5963x over previous
#include <cuda_runtime.h>
#include <cuda_fp16.h>
#include <math.h>
#include <stdint.h>

#define T_MAX 4096
#define E_NUM 8
#define D_DIM 1024
#define F_DIM 4096

// ---------------- scratch (static device globals; no allocs) ----------------
__device__ int   g_cnt[E_NUM];
__device__ int   g_tok[E_NUM * T_MAX];
__device__ int   g_aid[E_NUM * T_MAX];
__device__ float g_gate[2 * T_MAX];
// weights transposed to [E][N][K], fp16 (hi only; B-side unsplit)
__device__ __half g_W1h[(size_t)E_NUM * F_DIM * D_DIM];
__device__ __half g_W2h[(size_t)E_NUM * D_DIM * F_DIM];
// x pre-split into fp16 hi/lo
__device__ __half g_xh[(size_t)T_MAX * D_DIM];
__device__ __half g_xl[(size_t)T_MAX * D_DIM];
// hidden activations, split fp16: [2T][F]
__device__ __half g_hh[(size_t)2 * T_MAX * F_DIM];
__device__ __half g_hl[(size_t)2 * T_MAX * F_DIM];
__device__ float  g_y[(size_t)2 * T_MAX * D_DIM];

// ---------------- helpers ----------------
__device__ __forceinline__ uint32_t smem_u32(const void* p) {
    return (uint32_t)__cvta_generic_to_shared(p);
}
__device__ __forceinline__ void ldmat4(uint32_t (&r)[4], uint32_t addr) {
    asm volatile("ldmatrix.sync.aligned.m8n8.x4.shared.b16 {%0,%1,%2,%3}, [%4];"
        : "=r"(r[0]), "=r"(r[1]), "=r"(r[2]), "=r"(r[3]) : "r"(addr));
}
__device__ __forceinline__ void mma16816(float (&d)[4], const uint32_t (&a)[4],
                                         uint32_t b0, uint32_t b1) {
    asm volatile("mma.sync.aligned.m16n8k16.row.col.f32.f16.f16.f32 "
        "{%0,%1,%2,%3}, {%4,%5,%6,%7}, {%8,%9}, {%0,%1,%2,%3};"
        : "+f"(d[0]), "+f"(d[1]), "+f"(d[2]), "+f"(d[3])
        : "r"(a[0]), "r"(a[1]), "r"(a[2]), "r"(a[3]), "r"(b0), "r"(b1));
}
__device__ __forceinline__ void cp16(uint32_t dst, const void* src, uint32_t bytes) {
    asm volatile("cp.async.cg.shared.global [%0], [%1], 16, %2;"
        :: "r"(dst), "l"(src), "r"(bytes) : "memory");
}
__device__ __forceinline__ void cp_commit() {
    asm volatile("cp.async.commit_group;" ::: "memory");
}
__device__ __forceinline__ void cp_wait1() {
    asm volatile("cp.async.wait_group 1;" ::: "memory");
}
__device__ __forceinline__ uint32_t packh2(float a, float b) {
    __half2 h = __floats2half2_rn(a, b);
    return *(uint32_t*)&h;
}
__device__ __forceinline__ void splith(float v, __half& h, float& lo) {
    h = __float2half_rn(v);
    lo = v - __half2float(h);
}

// ---------------- init ----------------
__global__ void init_kernel() {
    if (threadIdx.x < E_NUM) g_cnt[threadIdx.x] = 0;
}

// ---------------- router ----------------
__global__ void router_kernel(const float* __restrict__ x,
                              const float* __restrict__ Wr,
                              const float* __restrict__ br, int T) {
    int warp = threadIdx.x >> 5;
    int lane = threadIdx.x & 31;
    int t = blockIdx.x * 8 + warp;
    if (t >= T) return;

    const float* xr = x + (size_t)t * D_DIM;
    float acc[E_NUM];
#pragma unroll
    for (int e = 0; e < E_NUM; e++) acc[e] = 0.f;
    for (int i = lane; i < D_DIM; i += 32) {
        float xv = xr[i];
        float4 w0 = *(const float4*)(Wr + (size_t)i * E_NUM);
        float4 w1 = *(const float4*)(Wr + (size_t)i * E_NUM + 4);
        acc[0] += xv * w0.x; acc[1] += xv * w0.y;
        acc[2] += xv * w0.z; acc[3] += xv * w0.w;
        acc[4] += xv * w1.x; acc[5] += xv * w1.y;
        acc[6] += xv * w1.z; acc[7] += xv * w1.w;
    }
#pragma unroll
    for (int e = 0; e < E_NUM; e++)
#pragma unroll
        for (int off = 16; off > 0; off >>= 1)
            acc[e] += __shfl_down_sync(0xffffffffu, acc[e], off);

    if (lane == 0) {
        float l[E_NUM], p[E_NUM];
        float mx = -1e30f;
#pragma unroll
        for (int e = 0; e < E_NUM; e++) { l[e] = acc[e] + br[e]; mx = fmaxf(mx, l[e]); }
        float s = 0.f;
#pragma unroll
        for (int e = 0; e < E_NUM; e++) { p[e] = expf(l[e] - mx); s += p[e]; }
        float inv = 1.f / s;
#pragma unroll
        for (int e = 0; e < E_NUM; e++) p[e] *= inv;
        float m1 = -1.f, m2 = -1.f;
#pragma unroll
        for (int e = 0; e < E_NUM; e++) {
            float v = p[e];
            if (v > m1) { m2 = m1; m1 = v; }
            else if (v > m2) { m2 = v; }
        }
        int j = 0;
#pragma unroll
        for (int e = 0; e < E_NUM; e++) {
            if (p[e] >= m2 && j < 2) {
                int slot = atomicAdd(&g_cnt[e], 1);
                g_tok[e * T_MAX + slot] = t;
                g_aid[e * T_MAX + slot] = t * 2 + j;
                g_gate[t * 2 + j] = p[e];
                j++;
            }
        }
    }
}

// ---------------- x split: fp32 -> fp16 hi/lo ----------------
__global__ void xsplit_kernel(const float* __restrict__ x) {
    int i = blockIdx.x * blockDim.x + threadIdx.x;  // over T*D/4
    const float4 v = ((const float4*)x)[i];
    __half h0, h1, h2, h3; float l0, l1, l2, l3;
    splith(v.x, h0, l0); splith(v.y, h1, l1);
    splith(v.z, h2, l2); splith(v.w, h3, l3);
    __half2 hp0 = __halves2half2(h0, h1), hp1 = __halves2half2(h2, h3);
    ((uint2*)g_xh)[i] = make_uint2(*(uint32_t*)&hp0, *(uint32_t*)&hp1);
    ((uint2*)g_xl)[i] = make_uint2(packh2(l0, l1), packh2(l2, l3));
}

// ---------------- weight prep: fp32 [E][K][N] -> fp16 [E][N][K] ----------------
__global__ void wprep_kernel(const float* __restrict__ W,
                             __half* __restrict__ Wh, int K, int N) {
    __shared__ float tile[32][33];
    int e = blockIdx.z;
    int n0 = blockIdx.x * 32;
    int k0 = blockIdx.y * 32;
#pragma unroll
    for (int r = 0; r < 4; r++) {
        int k = k0 + threadIdx.y + r * 8;
        tile[threadIdx.y + r * 8][threadIdx.x] =
            W[((size_t)e * K + k) * N + n0 + threadIdx.x];
    }
    __syncthreads();
#pragma unroll
    for (int r = 0; r < 4; r++) {
        int n = n0 + threadIdx.y + r * 8;
        int k = k0 + threadIdx.x;
        Wh[((size_t)e * N + n) * K + k] = __float2half_rn(tile[threadIdx.x][threadIdx.y + r * 8]);
    }
}

// ---------------- grouped MMA GEMM, cp.async 3-stage pipeline ----------------
// CTA tile 128(M) x 128(N), K staged by 32.
// D = A_hi*B + A_lo*B  (2-term split; B unsplit fp16)
template <int K, int NTOT, bool GELU_EPI, bool A_IS_H>
__global__ __launch_bounds__(256)
void moe_mma(const __half* __restrict__ Ah_all,
             const __half* __restrict__ Al_all,
             const __half* __restrict__ Bh_all,
             const float* __restrict__ bias_all) {
    constexpr int S = K / 32;
    constexpr int PITCH = 40;                  // halfs per row
    constexpr int TILE_B = 128 * PITCH * 2;    // 10240 B
    constexpr int STAGE = 3 * TILE_B;          // Ah, Al, Bh  = 30720 B
    extern __shared__ char sm[];

    const int e = blockIdx.z;
    const int cnt = g_cnt[e];
    const int m0 = blockIdx.y * 128;
    if (m0 >= cnt) return;
    const int n0 = blockIdx.x * 128;

    const int tid = threadIdx.x, wid = tid >> 5, lane = tid & 31;
    const int wm = wid & 3, wn = wid >> 2;     // warp grid 4(M) x 2(N)

    // staging map: thread -> row tid/2, k-half tid%2 (two 16B chunks each)
    const int grow = tid >> 1, gh = tid & 1;
    const bool avalid = (m0 + grow) < cnt;
    size_t arow_off = 0;
    if (avalid) {
        int ridx = A_IS_H ? g_aid[e * T_MAX + m0 + grow] : g_tok[e * T_MAX + m0 + grow];
        arow_off = (size_t)ridx * K;
    }
    const size_t brow_off = ((size_t)e * NTOT + n0 + grow) * K;
    const uint32_t st_off = (uint32_t)grow * (PITCH * 2) + gh * 32;
    const uint32_t smb = smem_u32(sm);
    const uint32_t abytes = avalid ? 16u : 0u;

    auto issue_stage = [&](int s) {
        const int b = s % 3;
        const int k0 = s * 32;
        const uint32_t ah = smb + b * STAGE + st_off;
        const uint32_t al = ah + TILE_B;
        const uint32_t bh = ah + 2 * TILE_B;
        const __half* pa = Ah_all + arow_off + k0 + gh * 16;
        const __half* pl = Al_all + arow_off + k0 + gh * 16;
        const __half* pb = Bh_all + brow_off + k0 + gh * 16;
        cp16(ah, pa, abytes);      cp16(ah + 16, pa + 8, abytes);
        cp16(al, pl, abytes);      cp16(al + 16, pl + 8, abytes);
        cp16(bh, pb, 16);          cp16(bh + 16, pb + 8, 16);
    };

    // ldmatrix lane addressing
    const int a_r = (lane & 7) + ((lane >> 3) & 1) * 8;
    const int a_c = lane >> 4;
    const int b_r = (lane & 7) + ((lane >> 4) << 3);
    const int b_c = (lane >> 3) & 1;

    float acc[2][8][4];
#pragma unroll
    for (int i = 0; i < 2; i++)
#pragma unroll
        for (int j = 0; j < 8; j++)
#pragma unroll
            for (int q = 0; q < 4; q++) acc[i][j][q] = 0.f;

    auto compute_stage = [&](int b) {
        const uint32_t ahb = smb + b * STAGE;
        const uint32_t alb = ahb + TILE_B, bhb = ahb + 2 * TILE_B;
#pragma unroll
        for (int ks = 0; ks < 2; ks++) {
            uint32_t a_hi[2][4], a_lo[2][4];
#pragma unroll
            for (int mt = 0; mt < 2; mt++) {
                uint32_t off = (uint32_t)((wm * 32 + mt * 16 + a_r) * PITCH + ks * 16 + a_c * 8) * 2;
                ldmat4(a_hi[mt], ahb + off);
                ldmat4(a_lo[mt], alb + off);
            }
#pragma unroll
            for (int nb = 0; nb < 4; nb++) {
                uint32_t off = (uint32_t)((wn * 64 + nb * 16 + b_r) * PITCH + ks * 16 + b_c * 8) * 2;
                uint32_t b_hi[4];
                ldmat4(b_hi, bhb + off);
#pragma unroll
                for (int mt = 0; mt < 2; mt++) {
                    mma16816(acc[mt][2 * nb],     a_hi[mt], b_hi[0], b_hi[1]);
                    mma16816(acc[mt][2 * nb + 1], a_hi[mt], b_hi[2], b_hi[3]);
                    mma16816(acc[mt][2 * nb],     a_lo[mt], b_hi[0], b_hi[1]);
                    mma16816(acc[mt][2 * nb + 1], a_lo[mt], b_hi[2], b_hi[3]);
                }
            }
        }
    };

    // pipeline: prologue 2 stages, then wait<=1 / sync / compute / issue+commit
    issue_stage(0); cp_commit();
    issue_stage(1); cp_commit();
    for (int s = 0; s < S; s++) {
        cp_wait1();
        __syncthreads();
        compute_stage(s % 3);
        if (s + 2 < S) issue_stage(s + 2);
        cp_commit();
    }

    // ---- epilogue ----
    const int r_l = lane >> 2, c_l = (lane & 3) * 2;
    const float* bias = bias_all + (size_t)e * NTOT;
#pragma unroll
    for (int mt = 0; mt < 2; mt++) {
#pragma unroll
        for (int rh = 0; rh < 2; rh++) {
            int gr = m0 + wm * 32 + mt * 16 + rh * 8 + r_l;
            if (gr >= cnt) continue;
            int aid = g_aid[e * T_MAX + gr];
#pragma unroll
            for (int nc = 0; nc < 8; nc++) {
                int gn = n0 + wn * 64 + nc * 8 + c_l;
                float v0 = acc[mt][nc][rh * 2]     + bias[gn];
                float v1 = acc[mt][nc][rh * 2 + 1] + bias[gn + 1];
                if (GELU_EPI) {
                    v0 = 0.5f * v0 * (1.f + erff(v0 * 0.70710678118654752f));
                    v1 = 0.5f * v1 * (1.f + erff(v1 * 0.70710678118654752f));
                    __half h0, h1; float l0, l1;
                    splith(v0, h0, l0); splith(v1, h1, l1);
                    __half2 hp = __halves2half2(h0, h1);
                    *(uint32_t*)(g_hh + (size_t)aid * NTOT + gn) = *(uint32_t*)&hp;
                    *(uint32_t*)(g_hl + (size_t)aid * NTOT + gn) = packh2(l0, l1);
                } else {
                    *(float2*)(g_y + (size_t)aid * NTOT + gn) = make_float2(v0, v1);
                }
            }
        }
    }
}

// ---------------- combine ----------------
__global__ void combine_kernel(float* __restrict__ out, int T) {
    int i = blockIdx.x * blockDim.x + threadIdx.x;
    int total = T * (D_DIM / 4);
    if (i >= total) return;
    int t = i / (D_DIM / 4);
    int c4 = i % (D_DIM / 4);
    float g0 = g_gate[2 * t], g1 = g_gate[2 * t + 1];
    const float4 y0 = *(const float4*)(g_y + (size_t)(2 * t) * D_DIM + c4 * 4);
    const float4 y1 = *(const float4*)(g_y + (size_t)(2 * t + 1) * D_DIM + c4 * 4);
    float4 o;
    o.x = g0 * y0.x + g1 * y1.x;
    o.y = g0 * y0.y + g1 * y1.y;
    o.z = g0 * y0.z + g1 * y1.z;
    o.w = g0 * y0.w + g1 * y1.w;
    ((float4*)out)[i] = o;
}

// ---------------- entry ----------------
extern "C" void kernel_launch(void* const* d_in, const int* in_sizes, int n_in,
                              void* d_out, int out_size) {
    const float* x  = (const float*)d_in[0];
    const float* Wr = (const float*)d_in[1];
    const float* br = (const float*)d_in[2];
    const float* W1 = (const float*)d_in[3];
    const float* b1 = (const float*)d_in[4];
    const float* W2 = (const float*)d_in[5];
    const float* b2 = (const float*)d_in[6];
    (void)n_in; (void)out_size;

    const int T = in_sizes[0] / D_DIM;

    const int SMEM = 3 * 3 * 128 * 40 * 2;   // 92160
    cudaFuncSetAttribute((const void*)&moe_mma<D_DIM, F_DIM, true, false>,
                         cudaFuncAttributeMaxDynamicSharedMemorySize, SMEM);
    cudaFuncSetAttribute((const void*)&moe_mma<F_DIM, D_DIM, false, true>,
                         cudaFuncAttributeMaxDynamicSharedMemorySize, SMEM);

    init_kernel<<<1, 32>>>();
    router_kernel<<<(T + 7) / 8, 256>>>(x, Wr, br, T);
    xsplit_kernel<<<(T * D_DIM / 4 + 255) / 256, 256>>>(x);

    __half* W1h; cudaGetSymbolAddress((void**)&W1h, g_W1h);
    __half* W2h; cudaGetSymbolAddress((void**)&W2h, g_W2h);
    __half* xh;  cudaGetSymbolAddress((void**)&xh,  g_xh);
    __half* xl;  cudaGetSymbolAddress((void**)&xl,  g_xl);
    __half* hh;  cudaGetSymbolAddress((void**)&hh,  g_hh);
    __half* hl;  cudaGetSymbolAddress((void**)&hl,  g_hl);

    wprep_kernel<<<dim3(F_DIM / 32, D_DIM / 32, E_NUM), dim3(32, 8)>>>(W1, W1h, D_DIM, F_DIM);
    wprep_kernel<<<dim3(D_DIM / 32, F_DIM / 32, E_NUM), dim3(32, 8)>>>(W2, W2h, F_DIM, D_DIM);

    moe_mma<D_DIM, F_DIM, true, false>
        <<<dim3(F_DIM / 128, T_MAX / 128, E_NUM), 256, SMEM>>>(xh, xl, W1h, b1);
    moe_mma<F_DIM, D_DIM, false, true>
        <<<dim3(D_DIM / 128, T_MAX / 128, E_NUM), 256, SMEM>>>(hh, hl, W2h, b2);

    int total = T * (D_DIM / 4);
    combine_kernel<<<(total + 255) / 256, 256>>>((float*)d_out, T);
}

// round 5
// speedup vs baseline: 5.2918x; 1.5299x over previous
#include <cuda_runtime.h>
#include <cuda_fp16.h>
#include <math.h>
#include <stdint.h>

#define T_MAX 4096
#define E_NUM 8
#define D_DIM 1024
#define F_DIM 4096

// ---------------- scratch (static device globals; no allocs) ----------------
__device__ int   g_cnt[E_NUM];
__device__ int   g_tok[E_NUM * T_MAX];
__device__ int   g_aid[E_NUM * T_MAX];
__device__ float g_gate[2 * T_MAX];
// weights transposed to [E][N][K], fp16
__device__ __half g_W1h[(size_t)E_NUM * F_DIM * D_DIM];
__device__ __half g_W2h[(size_t)E_NUM * D_DIM * F_DIM];
// x as fp16
__device__ __half g_xh[(size_t)T_MAX * D_DIM];
// hidden activations fp16: [2T][F]
__device__ __half g_hh[(size_t)2 * T_MAX * F_DIM];
__device__ float  g_y[(size_t)2 * T_MAX * D_DIM];

// ---------------- helpers ----------------
__device__ __forceinline__ uint32_t smem_u32(const void* p) {
    return (uint32_t)__cvta_generic_to_shared(p);
}
__device__ __forceinline__ void ldmat4(uint32_t (&r)[4], uint32_t addr) {
    asm volatile("ldmatrix.sync.aligned.m8n8.x4.shared.b16 {%0,%1,%2,%3}, [%4];"
        : "=r"(r[0]), "=r"(r[1]), "=r"(r[2]), "=r"(r[3]) : "r"(addr));
}
__device__ __forceinline__ void mma16816(float (&d)[4], const uint32_t (&a)[4],
                                         uint32_t b0, uint32_t b1) {
    asm volatile("mma.sync.aligned.m16n8k16.row.col.f32.f16.f16.f32 "
        "{%0,%1,%2,%3}, {%4,%5,%6,%7}, {%8,%9}, {%0,%1,%2,%3};"
        : "+f"(d[0]), "+f"(d[1]), "+f"(d[2]), "+f"(d[3])
        : "r"(a[0]), "r"(a[1]), "r"(a[2]), "r"(a[3]), "r"(b0), "r"(b1));
}
__device__ __forceinline__ void cp16(uint32_t dst, const void* src, uint32_t bytes) {
    asm volatile("cp.async.cg.shared.global [%0], [%1], 16, %2;"
        :: "r"(dst), "l"(src), "r"(bytes) : "memory");
}
__device__ __forceinline__ void cp_commit() {
    asm volatile("cp.async.commit_group;" ::: "memory");
}
__device__ __forceinline__ void cp_wait1() {
    asm volatile("cp.async.wait_group 1;" ::: "memory");
}
__device__ __forceinline__ uint32_t packh2(float a, float b) {
    __half2 h = __floats2half2_rn(a, b);
    return *(uint32_t*)&h;
}

// ---------------- init ----------------
__global__ void init_kernel() {
    if (threadIdx.x < E_NUM) g_cnt[threadIdx.x] = 0;
}

// ---------------- router ----------------
__global__ void router_kernel(const float* __restrict__ x,
                              const float* __restrict__ Wr,
                              const float* __restrict__ br, int T) {
    int warp = threadIdx.x >> 5;
    int lane = threadIdx.x & 31;
    int t = blockIdx.x * 8 + warp;
    if (t >= T) return;

    const float* xr = x + (size_t)t * D_DIM;
    float acc[E_NUM];
#pragma unroll
    for (int e = 0; e < E_NUM; e++) acc[e] = 0.f;
    for (int i = lane; i < D_DIM; i += 32) {
        float xv = xr[i];
        float4 w0 = *(const float4*)(Wr + (size_t)i * E_NUM);
        float4 w1 = *(const float4*)(Wr + (size_t)i * E_NUM + 4);
        acc[0] += xv * w0.x; acc[1] += xv * w0.y;
        acc[2] += xv * w0.z; acc[3] += xv * w0.w;
        acc[4] += xv * w1.x; acc[5] += xv * w1.y;
        acc[6] += xv * w1.z; acc[7] += xv * w1.w;
    }
#pragma unroll
    for (int e = 0; e < E_NUM; e++)
#pragma unroll
        for (int off = 16; off > 0; off >>= 1)
            acc[e] += __shfl_down_sync(0xffffffffu, acc[e], off);

    if (lane == 0) {
        float l[E_NUM], p[E_NUM];
        float mx = -1e30f;
#pragma unroll
        for (int e = 0; e < E_NUM; e++) { l[e] = acc[e] + br[e]; mx = fmaxf(mx, l[e]); }
        float s = 0.f;
#pragma unroll
        for (int e = 0; e < E_NUM; e++) { p[e] = expf(l[e] - mx); s += p[e]; }
        float inv = 1.f / s;
#pragma unroll
        for (int e = 0; e < E_NUM; e++) p[e] *= inv;
        float m1 = -1.f, m2 = -1.f;
#pragma unroll
        for (int e = 0; e < E_NUM; e++) {
            float v = p[e];
            if (v > m1) { m2 = m1; m1 = v; }
            else if (v > m2) { m2 = v; }
        }
        int j = 0;
#pragma unroll
        for (int e = 0; e < E_NUM; e++) {
            if (p[e] >= m2 && j < 2) {
                int slot = atomicAdd(&g_cnt[e], 1);
                g_tok[e * T_MAX + slot] = t;
                g_aid[e * T_MAX + slot] = t * 2 + j;
                g_gate[t * 2 + j] = p[e];
                j++;
            }
        }
    }
}

// ---------------- x convert: fp32 -> fp16 ----------------
__global__ void xconv_kernel(const float* __restrict__ x) {
    int i = blockIdx.x * blockDim.x + threadIdx.x;  // over T*D/4
    const float4 v = ((const float4*)x)[i];
    ((uint2*)g_xh)[i] = make_uint2(packh2(v.x, v.y), packh2(v.z, v.w));
}

// ---------------- weight prep: fp32 [E][K][N] -> fp16 [E][N][K] ----------------
__global__ void wprep_kernel(const float* __restrict__ W,
                             __half* __restrict__ Wh, int K, int N) {
    __shared__ float tile[32][33];
    int e = blockIdx.z;
    int n0 = blockIdx.x * 32;
    int k0 = blockIdx.y * 32;
#pragma unroll
    for (int r = 0; r < 4; r++) {
        int k = k0 + threadIdx.y + r * 8;
        tile[threadIdx.y + r * 8][threadIdx.x] =
            W[((size_t)e * K + k) * N + n0 + threadIdx.x];
    }
    __syncthreads();
#pragma unroll
    for (int r = 0; r < 4; r++) {
        int n = n0 + threadIdx.y + r * 8;
        int k = k0 + threadIdx.x;
        Wh[((size_t)e * N + n) * K + k] = __float2half_rn(tile[threadIdx.x][threadIdx.y + r * 8]);
    }
}

// ---------------- grouped MMA GEMM, cp.async 3-stage pipeline ----------------
// CTA tile 128(M) x 128(N), K staged by 32. Single fp16 term.
template <int K, int NTOT, bool GELU_EPI, bool A_IS_H>
__global__ __launch_bounds__(256, 2)
void moe_mma(const __half* __restrict__ Ah_all,
             const __half* __restrict__ Bh_all,
             const float* __restrict__ bias_all) {
    constexpr int S = K / 32;
    constexpr int PITCH = 40;                  // halfs per row
    constexpr int TILE_B = 128 * PITCH * 2;    // 10240 B
    constexpr int STAGE = 2 * TILE_B;          // Ah, Bh = 20480 B
    extern __shared__ char sm[];

    const int e = blockIdx.z;
    const int cnt = g_cnt[e];
    const int m0 = blockIdx.y * 128;
    if (m0 >= cnt) return;
    const int n0 = blockIdx.x * 128;

    const int tid = threadIdx.x, wid = tid >> 5, lane = tid & 31;
    const int wm = wid & 3, wn = wid >> 2;     // warp grid 4(M) x 2(N)

    // staging map: thread -> row tid/2, k-half tid%2 (two 16B chunks each)
    const int grow = tid >> 1, gh = tid & 1;
    const bool avalid = (m0 + grow) < cnt;
    size_t arow_off = 0;
    if (avalid) {
        int ridx = A_IS_H ? g_aid[e * T_MAX + m0 + grow] : g_tok[e * T_MAX + m0 + grow];
        arow_off = (size_t)ridx * K;
    }
    const size_t brow_off = ((size_t)e * NTOT + n0 + grow) * K;
    const uint32_t st_off = (uint32_t)grow * (PITCH * 2) + gh * 32;
    const uint32_t smb = smem_u32(sm);
    const uint32_t abytes = avalid ? 16u : 0u;

    auto issue_stage = [&](int s) {
        const int b = s % 3;
        const int k0 = s * 32;
        const uint32_t ah = smb + b * STAGE + st_off;
        const uint32_t bh = ah + TILE_B;
        const __half* pa = Ah_all + arow_off + k0 + gh * 16;
        const __half* pb = Bh_all + brow_off + k0 + gh * 16;
        cp16(ah, pa, abytes);      cp16(ah + 16, pa + 8, abytes);
        cp16(bh, pb, 16);          cp16(bh + 16, pb + 8, 16);
    };

    // ldmatrix lane addressing
    const int a_r = (lane & 7) + ((lane >> 3) & 1) * 8;
    const int a_c = lane >> 4;
    const int b_r = (lane & 7) + ((lane >> 4) << 3);
    const int b_c = (lane >> 3) & 1;

    float acc[2][8][4];
#pragma unroll
    for (int i = 0; i < 2; i++)
#pragma unroll
        for (int j = 0; j < 8; j++)
#pragma unroll
            for (int q = 0; q < 4; q++) acc[i][j][q] = 0.f;

    auto compute_stage = [&](int b) {
        const uint32_t ahb = smb + b * STAGE;
        const uint32_t bhb = ahb + TILE_B;
#pragma unroll
        for (int ks = 0; ks < 2; ks++) {
            uint32_t a_hi[2][4];
#pragma unroll
            for (int mt = 0; mt < 2; mt++) {
                uint32_t off = (uint32_t)((wm * 32 + mt * 16 + a_r) * PITCH + ks * 16 + a_c * 8) * 2;
                ldmat4(a_hi[mt], ahb + off);
            }
#pragma unroll
            for (int nb = 0; nb < 4; nb++) {
                uint32_t off = (uint32_t)((wn * 64 + nb * 16 + b_r) * PITCH + ks * 16 + b_c * 8) * 2;
                uint32_t b_hi[4];
                ldmat4(b_hi, bhb + off);
#pragma unroll
                for (int mt = 0; mt < 2; mt++) {
                    mma16816(acc[mt][2 * nb],     a_hi[mt], b_hi[0], b_hi[1]);
                    mma16816(acc[mt][2 * nb + 1], a_hi[mt], b_hi[2], b_hi[3]);
                }
            }
        }
    };

    // pipeline: prologue 2 stages, then wait<=1 / sync / compute / issue+commit
    issue_stage(0); cp_commit();
    issue_stage(1); cp_commit();
    for (int s = 0; s < S; s++) {
        cp_wait1();
        __syncthreads();
        compute_stage(s % 3);
        if (s + 2 < S) issue_stage(s + 2);
        cp_commit();
    }

    // ---- epilogue ----
    const int r_l = lane >> 2, c_l = (lane & 3) * 2;
    const float* bias = bias_all + (size_t)e * NTOT;
#pragma unroll
    for (int mt = 0; mt < 2; mt++) {
#pragma unroll
        for (int rh = 0; rh < 2; rh++) {
            int gr = m0 + wm * 32 + mt * 16 + rh * 8 + r_l;
            if (gr >= cnt) continue;
            int aid = g_aid[e * T_MAX + gr];
#pragma unroll
            for (int nc = 0; nc < 8; nc++) {
                int gn = n0 + wn * 64 + nc * 8 + c_l;
                float v0 = acc[mt][nc][rh * 2]     + bias[gn];
                float v1 = acc[mt][nc][rh * 2 + 1] + bias[gn + 1];
                if (GELU_EPI) {
                    v0 = 0.5f * v0 * (1.f + erff(v0 * 0.70710678118654752f));
                    v1 = 0.5f * v1 * (1.f + erff(v1 * 0.70710678118654752f));
                    *(uint32_t*)(g_hh + (size_t)aid * NTOT + gn) = packh2(v0, v1);
                } else {
                    *(float2*)(g_y + (size_t)aid * NTOT + gn) = make_float2(v0, v1);
                }
            }
        }
    }
}

// ---------------- combine ----------------
__global__ void combine_kernel(float* __restrict__ out, int T) {
    int i = blockIdx.x * blockDim.x + threadIdx.x;
    int total = T * (D_DIM / 4);
    if (i >= total) return;
    int t = i / (D_DIM / 4);
    int c4 = i % (D_DIM / 4);
    float g0 = g_gate[2 * t], g1 = g_gate[2 * t + 1];
    const float4 y0 = *(const float4*)(g_y + (size_t)(2 * t) * D_DIM + c4 * 4);
    const float4 y1 = *(const float4*)(g_y + (size_t)(2 * t + 1) * D_DIM + c4 * 4);
    float4 o;
    o.x = g0 * y0.x + g1 * y1.x;
    o.y = g0 * y0.y + g1 * y1.y;
    o.z = g0 * y0.z + g1 * y1.z;
    o.w = g0 * y0.w + g1 * y1.w;
    ((float4*)out)[i] = o;
}

// ---------------- entry ----------------
extern "C" void kernel_launch(void* const* d_in, const int* in_sizes, int n_in,
                              void* d_out, int out_size) {
    const float* x  = (const float*)d_in[0];
    const float* Wr = (const float*)d_in[1];
    const float* br = (const float*)d_in[2];
    const float* W1 = (const float*)d_in[3];
    const float* b1 = (const float*)d_in[4];
    const float* W2 = (const float*)d_in[5];
    const float* b2 = (const float*)d_in[6];
    (void)n_in; (void)out_size;

    const int T = in_sizes[0] / D_DIM;

    const int SMEM = 3 * 2 * 128 * 40 * 2;   // 61440
    cudaFuncSetAttribute((const void*)&moe_mma<D_DIM, F_DIM, true, false>,
                         cudaFuncAttributeMaxDynamicSharedMemorySize, SMEM);
    cudaFuncSetAttribute((const void*)&moe_mma<F_DIM, D_DIM, false, true>,
                         cudaFuncAttributeMaxDynamicSharedMemorySize, SMEM);

    init_kernel<<<1, 32>>>();
    router_kernel<<<(T + 7) / 8, 256>>>(x, Wr, br, T);
    xconv_kernel<<<(T * D_DIM / 4 + 255) / 256, 256>>>(x);

    __half* W1h; cudaGetSymbolAddress((void**)&W1h, g_W1h);
    __half* W2h; cudaGetSymbolAddress((void**)&W2h, g_W2h);
    __half* xh;  cudaGetSymbolAddress((void**)&xh,  g_xh);
    __half* hh;  cudaGetSymbolAddress((void**)&hh,  g_hh);

    wprep_kernel<<<dim3(F_DIM / 32, D_DIM / 32, E_NUM), dim3(32, 8)>>>(W1, W1h, D_DIM, F_DIM);
    wprep_kernel<<<dim3(D_DIM / 32, F_DIM / 32, E_NUM), dim3(32, 8)>>>(W2, W2h, F_DIM, D_DIM);

    moe_mma<D_DIM, F_DIM, true, false>
        <<<dim3(F_DIM / 128, T_MAX / 128, E_NUM), 256, SMEM>>>(xh, W1h, b1);
    moe_mma<F_DIM, D_DIM, false, true>
        <<<dim3(D_DIM / 128, T_MAX / 128, E_NUM), 256, SMEM>>>(hh, W2h, b2);

    int total = T * (D_DIM / 4);
    combine_kernel<<<(total + 255) / 256, 256>>>((float*)d_out, T);
}

// round 6
// speedup vs baseline: 5.7168x; 1.0803x over previous
#include <cuda_runtime.h>
#include <cuda_fp16.h>
#include <math.h>
#include <stdint.h>

#define T_MAX 4096
#define E_NUM 8
#define D_DIM 1024
#define F_DIM 4096

// ---------------- scratch (static device globals; no allocs) ----------------
__device__ int   g_cnt[E_NUM];
__device__ int   g_tok[E_NUM * T_MAX];
__device__ int   g_aid[E_NUM * T_MAX];
__device__ float g_gate[2 * T_MAX];
// weights as fp16, SAME layout as input: [E][K][N]
__device__ __half g_W1h[(size_t)E_NUM * D_DIM * F_DIM];
__device__ __half g_W2h[(size_t)E_NUM * F_DIM * D_DIM];
// x as fp16
__device__ __half g_xh[(size_t)T_MAX * D_DIM];
// hidden activations fp16: [2T][F]
__device__ __half g_hh[(size_t)2 * T_MAX * F_DIM];
__device__ float  g_y[(size_t)2 * T_MAX * D_DIM];

// ---------------- helpers ----------------
__device__ __forceinline__ uint32_t smem_u32(const void* p) {
    return (uint32_t)__cvta_generic_to_shared(p);
}
__device__ __forceinline__ void ldmat4(uint32_t (&r)[4], uint32_t addr) {
    asm volatile("ldmatrix.sync.aligned.m8n8.x4.shared.b16 {%0,%1,%2,%3}, [%4];"
        : "=r"(r[0]), "=r"(r[1]), "=r"(r[2]), "=r"(r[3]) : "r"(addr));
}
__device__ __forceinline__ void ldmat4t(uint32_t (&r)[4], uint32_t addr) {
    asm volatile("ldmatrix.sync.aligned.m8n8.x4.trans.shared.b16 {%0,%1,%2,%3}, [%4];"
        : "=r"(r[0]), "=r"(r[1]), "=r"(r[2]), "=r"(r[3]) : "r"(addr));
}
__device__ __forceinline__ void mma16816(float (&d)[4], const uint32_t (&a)[4],
                                         uint32_t b0, uint32_t b1) {
    asm volatile("mma.sync.aligned.m16n8k16.row.col.f32.f16.f16.f32 "
        "{%0,%1,%2,%3}, {%4,%5,%6,%7}, {%8,%9}, {%0,%1,%2,%3};"
        : "+f"(d[0]), "+f"(d[1]), "+f"(d[2]), "+f"(d[3])
        : "r"(a[0]), "r"(a[1]), "r"(a[2]), "r"(a[3]), "r"(b0), "r"(b1));
}
__device__ __forceinline__ void cp16(uint32_t dst, const void* src, uint32_t bytes) {
    asm volatile("cp.async.cg.shared.global [%0], [%1], 16, %2;"
        :: "r"(dst), "l"(src), "r"(bytes) : "memory");
}
__device__ __forceinline__ void cp_commit() {
    asm volatile("cp.async.commit_group;" ::: "memory");
}
__device__ __forceinline__ void cp_wait1() {
    asm volatile("cp.async.wait_group 1;" ::: "memory");
}
__device__ __forceinline__ uint32_t packh2(float a, float b) {
    __half2 h = __floats2half2_rn(a, b);
    return *(uint32_t*)&h;
}

// ---------------- x convert (also zeroes g_cnt; runs before router) ----------------
__global__ void xconv_kernel(const float* __restrict__ x) {
    int i = blockIdx.x * blockDim.x + threadIdx.x;  // over T*D/4
    if (blockIdx.x == 0 && threadIdx.x < E_NUM) g_cnt[threadIdx.x] = 0;
    const float4 v = ((const float4*)x)[i];
    ((uint2*)g_xh)[i] = make_uint2(packh2(v.x, v.y), packh2(v.z, v.w));
}

// ---------------- router ----------------
__global__ void router_kernel(const float* __restrict__ x,
                              const float* __restrict__ Wr,
                              const float* __restrict__ br, int T) {
    int warp = threadIdx.x >> 5;
    int lane = threadIdx.x & 31;
    int t = blockIdx.x * 8 + warp;
    if (t >= T) return;

    const float* xr = x + (size_t)t * D_DIM;
    float acc[E_NUM];
#pragma unroll
    for (int e = 0; e < E_NUM; e++) acc[e] = 0.f;
    for (int i = lane; i < D_DIM; i += 32) {
        float xv = xr[i];
        float4 w0 = *(const float4*)(Wr + (size_t)i * E_NUM);
        float4 w1 = *(const float4*)(Wr + (size_t)i * E_NUM + 4);
        acc[0] += xv * w0.x; acc[1] += xv * w0.y;
        acc[2] += xv * w0.z; acc[3] += xv * w0.w;
        acc[4] += xv * w1.x; acc[5] += xv * w1.y;
        acc[6] += xv * w1.z; acc[7] += xv * w1.w;
    }
#pragma unroll
    for (int e = 0; e < E_NUM; e++)
#pragma unroll
        for (int off = 16; off > 0; off >>= 1)
            acc[e] += __shfl_down_sync(0xffffffffu, acc[e], off);

    if (lane == 0) {
        float l[E_NUM], p[E_NUM];
        float mx = -1e30f;
#pragma unroll
        for (int e = 0; e < E_NUM; e++) { l[e] = acc[e] + br[e]; mx = fmaxf(mx, l[e]); }
        float s = 0.f;
#pragma unroll
        for (int e = 0; e < E_NUM; e++) { p[e] = expf(l[e] - mx); s += p[e]; }
        float inv = 1.f / s;
#pragma unroll
        for (int e = 0; e < E_NUM; e++) p[e] *= inv;
        float m1 = -1.f, m2 = -1.f;
#pragma unroll
        for (int e = 0; e < E_NUM; e++) {
            float v = p[e];
            if (v > m1) { m2 = m1; m1 = v; }
            else if (v > m2) { m2 = v; }
        }
        int j = 0;
#pragma unroll
        for (int e = 0; e < E_NUM; e++) {
            if (p[e] >= m2 && j < 2) {
                int slot = atomicAdd(&g_cnt[e], 1);
                g_tok[e * T_MAX + slot] = t;
                g_aid[e * T_MAX + slot] = t * 2 + j;
                g_gate[t * 2 + j] = p[e];
                j++;
            }
        }
    }
}

// ---------------- weight convert: fp32 -> fp16, SAME layout (no transpose) ----------------
__global__ void wconv_kernel(const float* __restrict__ W, __half* __restrict__ Wh) {
    int i = blockIdx.x * blockDim.x + threadIdx.x;   // over total/4
    const float4 v = ((const float4*)W)[i];
    ((uint2*)Wh)[i] = make_uint2(packh2(v.x, v.y), packh2(v.z, v.w));
}

// ---------------- grouped MMA GEMM, cp.async 3-stage pipeline ----------------
// CTA tile 128(M) x 128(N), K staged by 32.
// A: gathered rows [M][K] (PITCH_A=40), non-trans ldmatrix.
// B: weights [E][K][N] row-major, staged as [32][136], trans ldmatrix.
template <int K, int NTOT, bool GELU_EPI, bool A_IS_H>
__global__ __launch_bounds__(256, 2)
void moe_mma(const __half* __restrict__ Ah_all,
             const __half* __restrict__ Bh_all,
             const float* __restrict__ bias_all) {
    constexpr int S = K / 32;
    constexpr int PITCH_A = 40;                     // halfs
    constexpr int PITCH_B = 136;                    // halfs (272B rows: conflict-free)
    constexpr int A_TILE = 128 * PITCH_A * 2;       // 10240 B
    constexpr int B_TILE = 32 * PITCH_B * 2;        // 8704 B
    constexpr int STAGE = A_TILE + B_TILE;          // 18944 B
    extern __shared__ char sm[];

    const int e = blockIdx.z;
    const int cnt = g_cnt[e];
    const int m0 = blockIdx.y * 128;
    if (m0 >= cnt) return;
    const int n0 = blockIdx.x * 128;

    const int tid = threadIdx.x, wid = tid >> 5, lane = tid & 31;
    const int wm = wid & 3, wn = wid >> 2;          // warp grid 4(M) x 2(N)

    // A staging: thread -> row tid/2, k-half tid%2 (two 16B chunks)
    const int grow = tid >> 1, gh = tid & 1;
    const bool avalid = (m0 + grow) < cnt;
    size_t arow_off = 0;
    if (avalid) {
        int ridx = A_IS_H ? g_aid[e * T_MAX + m0 + grow] : g_tok[e * T_MAX + m0 + grow];
        arow_off = (size_t)ridx * K;
    }
    const uint32_t a_st = (uint32_t)grow * (PITCH_A * 2) + gh * 32;
    const uint32_t abytes = avalid ? 16u : 0u;

    // B staging: thread -> k-row tid/8, 32B chunk (tid&7)
    const int brow = tid >> 3, bcol = (tid & 7) * 16;       // bcol in halfs
    const __half* bbase = Bh_all + ((size_t)e * K + brow) * NTOT + n0 + bcol;
    const uint32_t b_st = (uint32_t)(brow * PITCH_B + bcol) * 2;

    const uint32_t smb = smem_u32(sm);

    auto issue_stage = [&](int s) {
        const int b = s % 3;
        const int k0 = s * 32;
        const uint32_t ah = smb + b * STAGE + a_st;
        const __half* pa = Ah_all + arow_off + k0 + gh * 16;
        cp16(ah, pa, abytes);      cp16(ah + 16, pa + 8, abytes);
        const uint32_t bh = smb + b * STAGE + A_TILE + b_st;
        const __half* pb = bbase + (size_t)k0 * NTOT;
        cp16(bh, pb, 16);          cp16(bh + 16, pb + 8, 16);
    };

    // ldmatrix lane addressing
    const int a_r = (lane & 7) + ((lane >> 3) & 1) * 8;     // A row within 16
    const int a_c = lane >> 4;                              // A k-chunk (8 halfs)
    const int bt_k = ((lane >> 3) & 1) * 8 + (lane & 7);    // B k-row within 16
    const int bt_n = (lane >> 4) * 8;                       // B n-offset within 16

    float acc[2][8][4];
#pragma unroll
    for (int i = 0; i < 2; i++)
#pragma unroll
        for (int j = 0; j < 8; j++)
#pragma unroll
            for (int q = 0; q < 4; q++) acc[i][j][q] = 0.f;

    auto compute_stage = [&](int b) {
        const uint32_t ahb = smb + b * STAGE;
        const uint32_t bhb = ahb + A_TILE;
#pragma unroll
        for (int ks = 0; ks < 2; ks++) {
            uint32_t a_hi[2][4];
#pragma unroll
            for (int mt = 0; mt < 2; mt++) {
                uint32_t off = (uint32_t)((wm * 32 + mt * 16 + a_r) * PITCH_A + ks * 16 + a_c * 8) * 2;
                ldmat4(a_hi[mt], ahb + off);
            }
#pragma unroll
            for (int nb = 0; nb < 4; nb++) {
                uint32_t off = (uint32_t)((ks * 16 + bt_k) * PITCH_B + wn * 64 + nb * 16 + bt_n) * 2;
                uint32_t b_hi[4];
                ldmat4t(b_hi, bhb + off);
#pragma unroll
                for (int mt = 0; mt < 2; mt++) {
                    mma16816(acc[mt][2 * nb],     a_hi[mt], b_hi[0], b_hi[1]);
                    mma16816(acc[mt][2 * nb + 1], a_hi[mt], b_hi[2], b_hi[3]);
                }
            }
        }
    };

    // pipeline: prologue 2 stages, then wait<=1 / sync / compute / issue+commit
    issue_stage(0); cp_commit();
    issue_stage(1); cp_commit();
    for (int s = 0; s < S; s++) {
        cp_wait1();
        __syncthreads();
        compute_stage(s % 3);
        if (s + 2 < S) issue_stage(s + 2);
        cp_commit();
    }

    // ---- epilogue ----
    const int r_l = lane >> 2, c_l = (lane & 3) * 2;
    const float* bias = bias_all + (size_t)e * NTOT;
#pragma unroll
    for (int mt = 0; mt < 2; mt++) {
#pragma unroll
        for (int rh = 0; rh < 2; rh++) {
            int gr = m0 + wm * 32 + mt * 16 + rh * 8 + r_l;
            if (gr >= cnt) continue;
            int aid = g_aid[e * T_MAX + gr];
#pragma unroll
            for (int nc = 0; nc < 8; nc++) {
                int gn = n0 + wn * 64 + nc * 8 + c_l;
                float v0 = acc[mt][nc][rh * 2]     + bias[gn];
                float v1 = acc[mt][nc][rh * 2 + 1] + bias[gn + 1];
                if (GELU_EPI) {
                    v0 = 0.5f * v0 * (1.f + erff(v0 * 0.70710678118654752f));
                    v1 = 0.5f * v1 * (1.f + erff(v1 * 0.70710678118654752f));
                    *(uint32_t*)(g_hh + (size_t)aid * NTOT + gn) = packh2(v0, v1);
                } else {
                    *(float2*)(g_y + (size_t)aid * NTOT + gn) = make_float2(v0, v1);
                }
            }
        }
    }
}

// ---------------- combine ----------------
__global__ void combine_kernel(float* __restrict__ out, int T) {
    int i = blockIdx.x * blockDim.x + threadIdx.x;
    int total = T * (D_DIM / 4);
    if (i >= total) return;
    int t = i / (D_DIM / 4);
    int c4 = i % (D_DIM / 4);
    float g0 = g_gate[2 * t], g1 = g_gate[2 * t + 1];
    const float4 y0 = *(const float4*)(g_y + (size_t)(2 * t) * D_DIM + c4 * 4);
    const float4 y1 = *(const float4*)(g_y + (size_t)(2 * t + 1) * D_DIM + c4 * 4);
    float4 o;
    o.x = g0 * y0.x + g1 * y1.x;
    o.y = g0 * y0.y + g1 * y1.y;
    o.z = g0 * y0.z + g1 * y1.z;
    o.w = g0 * y0.w + g1 * y1.w;
    ((float4*)out)[i] = o;
}

// ---------------- entry ----------------
extern "C" void kernel_launch(void* const* d_in, const int* in_sizes, int n_in,
                              void* d_out, int out_size) {
    const float* x  = (const float*)d_in[0];
    const float* Wr = (const float*)d_in[1];
    const float* br = (const float*)d_in[2];
    const float* W1 = (const float*)d_in[3];
    const float* b1 = (const float*)d_in[4];
    const float* W2 = (const float*)d_in[5];
    const float* b2 = (const float*)d_in[6];
    (void)n_in; (void)out_size;

    const int T = in_sizes[0] / D_DIM;

    const int SMEM = 3 * (128 * 40 * 2 + 32 * 136 * 2);   // 56832
    cudaFuncSetAttribute((const void*)&moe_mma<D_DIM, F_DIM, true, false>,
                         cudaFuncAttributeMaxDynamicSharedMemorySize, SMEM);
    cudaFuncSetAttribute((const void*)&moe_mma<F_DIM, D_DIM, false, true>,
                         cudaFuncAttributeMaxDynamicSharedMemorySize, SMEM);

    xconv_kernel<<<(T * D_DIM / 4 + 255) / 256, 256>>>(x);   // also zeroes g_cnt
    router_kernel<<<(T + 7) / 8, 256>>>(x, Wr, br, T);

    __half* W1h; cudaGetSymbolAddress((void**)&W1h, g_W1h);
    __half* W2h; cudaGetSymbolAddress((void**)&W2h, g_W2h);
    __half* xh;  cudaGetSymbolAddress((void**)&xh,  g_xh);
    __half* hh;  cudaGetSymbolAddress((void**)&hh,  g_hh);

    const int wtot = E_NUM * D_DIM * F_DIM / 4;
    wconv_kernel<<<wtot / 256, 256>>>(W1, W1h);
    wconv_kernel<<<wtot / 256, 256>>>(W2, W2h);

    moe_mma<D_DIM, F_DIM, true, false>
        <<<dim3(F_DIM / 128, T_MAX / 128, E_NUM), 256, SMEM>>>(xh, W1h, b1);
    moe_mma<F_DIM, D_DIM, false, true>
        <<<dim3(D_DIM / 128, T_MAX / 128, E_NUM), 256, SMEM>>>(hh, W2h, b2);

    int total = T * (D_DIM / 4);
    combine_kernel<<<(total + 255) / 256, 256>>>((float*)d_out, T);
}